// round 14
// baseline (speedup 1.0000x reference)
#include <cuda_runtime.h>

// CapsuleLayer: x[B,I,D] fp32, W[I,O,D,K] fp32 -> v[B,O,K] fp32
// B=64, I=2048, D=8, O=32, K=16, 3 routing rounds.
// Routing logits linear in v => each round is one fused sweep over i.
// Round 14: R13 (chunk-major smem W: W_sm[cnk][o][4] -> warp's 4 o-lanes
// read ONE 128B region per LDS = 1 L1 wavefront, vs 4 in R11) with the
// x-tile indexing bug fixed (float4 index arithmetic: b=tb+8 is xb[tb+8],
// not xh0[2]).

#define BB 64
#define II 2048
#define DD 8
#define OO 32
#define KK 16
#define BG 16            // b's per block (2 per thread)
#define GX 74            // i-blocks; grid = 74 x 4 = 296 = 148 SMs x 2
#define NBUF 3
#define SVOL (BB*OO*KK)  // 32768

#define WSLABF (32*128)           // 4096 floats: [cnk=32][o=32][4]
#define XSLABF (2*BG*4)           // 128 floats:  [half=2][b=16][4]
#define SLABF  (WSLABF + XSLABF)  // 4224 floats
#define AG_OFF (NBUF*SLABF)       // 12672 floats
#define AGROW  33
#define SMEM_BYTES ((AG_OFF + BG*AGROW) * 4)   // 52800 B

__device__ float g_part[GX * SVOL];  // per-i-block partial s (9.7 MB)
__device__ float g_vsum[SVOL];       // running sum of squashed v's

// ---------- packed f32x2 helpers ----------
__device__ __forceinline__ unsigned long long pk2(float lo, float hi) {
    unsigned long long r;
    asm("mov.b64 %0, {%1, %2};" : "=l"(r) : "f"(lo), "f"(hi));
    return r;
}
__device__ __forceinline__ void upk2(unsigned long long v, float& lo, float& hi) {
    asm("mov.b64 {%0, %1}, %2;" : "=f"(lo), "=f"(hi) : "l"(v));
}
__device__ __forceinline__ unsigned long long fma2(unsigned long long a,
                                                   unsigned long long b,
                                                   unsigned long long c) {
    unsigned long long d;
    asm("fma.rn.f32x2 %0, %1, %2, %3;" : "=l"(d) : "l"(a), "l"(b), "l"(c));
    return d;
}

// ---------- cp.async helpers ----------
__device__ __forceinline__ void cp16(unsigned dst_smem, const void* src) {
    asm volatile("cp.async.cg.shared.global [%0], [%1], 16;"
                 :: "r"(dst_smem), "l"(src));
}
__device__ __forceinline__ void cp_commit() {
    asm volatile("cp.async.commit_group;");
}
template<int N>
__device__ __forceinline__ void cp_wait() {
    asm volatile("cp.async.wait_group %0;" :: "n"(N) : "memory");
}

// Stage one i (W tile + x column) into buffer `buf`. One commit group.
// W: 1024 16B-chunks. Source chunk (o, cnk) -> dst cnk*128 + o*4 floats
// (chunk-major transpose). x: 32 chunks -> [half][b][4].
__device__ __forceinline__ void fill_slab(unsigned sm_addr,
                                          const float* __restrict__ W,
                                          const float* __restrict__ x,
                                          int i, int buf, int t, int bg) {
#pragma unroll
    for (int r = 0; r < 4; r++) {
        int c = t + r * 256;
        int o = c >> 5, cnk = c & 31;
        const float* src = W + ((size_t)i * OO + o) * (DD * KK) + cnk * 4;
        unsigned dst = sm_addr + (unsigned)((buf * SLABF + cnk * 128 + o * 4) * 4);
        cp16(dst, src);
    }
    if (t < BG * 2) {
        int b = t >> 1, half = t & 1;
        const float* src = x + ((size_t)(bg * BG + b) * II + i) * DD + half * 4;
        unsigned dst = sm_addr +
            (unsigned)((buf * SLABF + WSLABF + half * 64 + b * 4) * 4);
        cp16(dst, src);
    }
    cp_commit();
}

// Fused routing pass. 256 threads: t = o*8 + tb; thread handles b = tb, tb+8.
// Warp = 4 o x 8 tb. Chunk-major W: each W-LDS touches ONE 128B region.
template<bool FIRST>
__global__ __launch_bounds__(256, 2)
void pass_kernel(const float* __restrict__ x, const float* __restrict__ W) {
    extern __shared__ float sm[];
    const unsigned sm_addr = (unsigned)__cvta_generic_to_shared(sm);
    float* ag = sm + AG_OFF;

    const int t  = threadIdx.x;
    const int o  = t >> 3;
    const int tb = t & 7;
    const int bg = blockIdx.y;
    const int b0 = bg * BG + tb;
    const int b1 = b0 + 8;

    // variable i-range: block bx handles [ib, ie)  (27 or 28 i's)
    const int bx = blockIdx.x;
    const int ib = (bx * II) / GX;
    const int ie = ((bx + 1) * II) / GX;
    const int cnt = ie - ib;

    fill_slab(sm_addr, W, x, ib,     0, t, bg);
    fill_slab(sm_addr, W, x, ib + 1, 1, t, bg);

    unsigned long long Va[8], Vb[8];
    if (!FIRST) {
        const ulonglong2* vp0 =
            reinterpret_cast<const ulonglong2*>(g_vsum + ((size_t)b0 * OO + o) * KK);
        const ulonglong2* vp1 =
            reinterpret_cast<const ulonglong2*>(g_vsum + ((size_t)b1 * OO + o) * KK);
#pragma unroll
        for (int j = 0; j < 4; j++) {
            ulonglong2 q0 = vp0[j]; Va[2*j] = q0.x; Va[2*j+1] = q0.y;
            ulonglong2 q1 = vp1[j]; Vb[2*j] = q1.x; Vb[2*j+1] = q1.y;
        }
    }

    unsigned long long sa[8], sb[8];
#pragma unroll
    for (int j = 0; j < 8; j++) { sa[j] = 0ull; sb[j] = 0ull; }

    for (int s = 0; s < cnt; s++) {
        if (s + 1 < cnt) cp_wait<1>(); else cp_wait<0>();
        __syncthreads();   // slab s resident; all warps done with slab s-1
        if (s + 2 < cnt)
            fill_slab(sm_addr, W, x, ib + s + 2, (s + 2) % NBUF, t, bg);

        const float* slab = sm + (s % NBUF) * SLABF;

        // x tile: [half][b][4]; as float4 array, half stride = 16, b index = b.
        float xf0[8], xf1[8];
        {
            const float4* xb = reinterpret_cast<const float4*>(slab + WSLABF);
            float4 a0 = xb[tb];            // b0, d0..3
            float4 a1 = xb[16 + tb];       // b0, d4..7
            float4 c0 = xb[tb + 8];        // b1, d0..3
            float4 c1 = xb[16 + tb + 8];   // b1, d4..7
            xf0[0]=a0.x; xf0[1]=a0.y; xf0[2]=a0.z; xf0[3]=a0.w;
            xf0[4]=a1.x; xf0[5]=a1.y; xf0[6]=a1.z; xf0[7]=a1.w;
            xf1[0]=c0.x; xf1[1]=c0.y; xf1[2]=c0.z; xf1[3]=c0.w;
            xf1[4]=c1.x; xf1[5]=c1.y; xf1[6]=c1.z; xf1[7]=c1.w;
        }

        unsigned long long ua[8], ub[8];
#pragma unroll
        for (int j = 0; j < 8; j++) { ua[j] = 0ull; ub[j] = 0ull; }

        // W: chunk cnk = d*4+q at [cnk*128 + o*4]; one LDS.128 = k-quad (2 ull)
        const float* wbase = slab + o * 4;
#pragma unroll
        for (int d = 0; d < DD; d++) {
            unsigned long long xa2 = pk2(xf0[d], xf0[d]);
            unsigned long long xb2 = pk2(xf1[d], xf1[d]);
#pragma unroll
            for (int q = 0; q < 4; q++) {
                ulonglong2 wv = *reinterpret_cast<const ulonglong2*>(
                    wbase + (d * 4 + q) * 128);
                ua[2*q]   = fma2(xa2, wv.x, ua[2*q]);
                ub[2*q]   = fma2(xb2, wv.x, ub[2*q]);
                ua[2*q+1] = fma2(xa2, wv.y, ua[2*q+1]);
                ub[2*q+1] = fma2(xb2, wv.y, ub[2*q+1]);
            }
        }

        unsigned long long c2a, c2b;
        if (FIRST) {
            c2a = pk2(1.0f / OO, 1.0f / OO);
            c2b = c2a;
        } else {
            unsigned long long acca = 0ull, accb = 0ull;
#pragma unroll
            for (int j = 0; j < 8; j++) {
                acca = fma2(ua[j], Va[j], acca);
                accb = fma2(ub[j], Vb[j], accb);
            }
            float al, ah, bl2, bh;
            upk2(acca, al, ah);
            upk2(accb, bl2, bh);
            ag[tb * AGROW + o]       = al + ah;
            ag[(tb + 8) * AGROW + o] = bl2 + bh;
            __syncthreads();                 // barrier 1: agr visible

            // warp w: softmax rows w, w+8 (lane = o). No max-subtract:
            // |agr| <= |u||Vsum| = O(1), exp safe in fp32.
            {
                int sw = t >> 5, lane = t & 31;
                float e0 = __expf(ag[sw * AGROW + lane]);
                float e1 = __expf(ag[(sw + 8) * AGROW + lane]);
                float s0 = e0, s1 = e1;
#pragma unroll
                for (int st = 16; st > 0; st >>= 1) {
                    s0 += __shfl_xor_sync(0xffffffffu, s0, st);
                    s1 += __shfl_xor_sync(0xffffffffu, s1, st);
                }
                ag[sw * AGROW + lane]       = __fdividef(e0, s0);
                ag[(sw + 8) * AGROW + lane] = __fdividef(e1, s1);
            }
            __syncthreads();                 // barrier 2: c visible

            float ca = ag[tb * AGROW + o];
            float cb = ag[(tb + 8) * AGROW + o];
            c2a = pk2(ca, ca);
            c2b = pk2(cb, cb);
        }

#pragma unroll
        for (int j = 0; j < 8; j++) {
            sa[j] = fma2(c2a, ua[j], sa[j]);
            sb[j] = fma2(c2b, ub[j], sb[j]);
        }
    }

    ulonglong2* p0 = reinterpret_cast<ulonglong2*>(
        g_part + ((size_t)bx * SVOL + ((size_t)b0 * OO + o) * KK));
    ulonglong2* p1 = reinterpret_cast<ulonglong2*>(
        g_part + ((size_t)bx * SVOL + ((size_t)b1 * OO + o) * KK));
    p0[0] = make_ulonglong2(sa[0], sa[1]);
    p0[1] = make_ulonglong2(sa[2], sa[3]);
    p0[2] = make_ulonglong2(sa[4], sa[5]);
    p0[3] = make_ulonglong2(sa[6], sa[7]);
    p1[0] = make_ulonglong2(sb[0], sb[1]);
    p1[1] = make_ulonglong2(sb[2], sb[3]);
    p1[2] = make_ulonglong2(sb[4], sb[5]);
    p1[3] = make_ulonglong2(sb[6], sb[7]);
}

// Reduce partials over GX=74 slabs (8 independent chains for MLP), squash K=16.
// phase 0: vsum = v ; phase 1: vsum += v ; phase 2: out = v
__global__ void squash_kernel(float* __restrict__ out, int phase) {
    int idx = blockIdx.x * 256 + threadIdx.x;   // (b*O+o)*K + k
    float a0 = 0.f, a1 = 0.f, a2 = 0.f, a3 = 0.f;
    float a4 = 0.f, a5 = 0.f, a6 = 0.f, a7 = 0.f;
#pragma unroll
    for (int p = 0; p + 8 <= GX; p += 8) {      // p = 0..64, covers 0..71
        a0 += g_part[(size_t)(p + 0) * SVOL + idx];
        a1 += g_part[(size_t)(p + 1) * SVOL + idx];
        a2 += g_part[(size_t)(p + 2) * SVOL + idx];
        a3 += g_part[(size_t)(p + 3) * SVOL + idx];
        a4 += g_part[(size_t)(p + 4) * SVOL + idx];
        a5 += g_part[(size_t)(p + 5) * SVOL + idx];
        a6 += g_part[(size_t)(p + 6) * SVOL + idx];
        a7 += g_part[(size_t)(p + 7) * SVOL + idx];
    }
    a0 += g_part[(size_t)72 * SVOL + idx];
    a1 += g_part[(size_t)73 * SVOL + idx];
    float s = ((a0 + a1) + (a2 + a3)) + ((a4 + a5) + (a6 + a7));

    float s2 = s * s;
    s2 += __shfl_xor_sync(0xffffffffu, s2, 1);
    s2 += __shfl_xor_sync(0xffffffffu, s2, 2);
    s2 += __shfl_xor_sync(0xffffffffu, s2, 4);
    s2 += __shfl_xor_sync(0xffffffffu, s2, 8);

    float scale = s2 / ((1.0f + s2) * sqrtf(s2 + 1e-7f));
    float v = scale * s;

    if (phase == 0)      g_vsum[idx] = v;
    else if (phase == 1) g_vsum[idx] += v;
    else                 out[idx] = v;
}

// No-op: keeps ncu's -s 5 -c 1 capture window on pass#3 (softmax pass).
__global__ void dummy_kernel() {}

extern "C" void kernel_launch(void* const* d_in, const int* in_sizes, int n_in,
                              void* d_out, int out_size) {
    const float* a0 = (const float*)d_in[0];
    const float* a1 = (const float*)d_in[1];
    const float* x;
    const float* W;
    if (in_sizes[0] == BB * II * DD) { x = a0; W = a1; }
    else                             { x = a1; W = a0; }
    float* out = (float*)d_out;

    cudaFuncSetAttribute(pass_kernel<true>,
                         cudaFuncAttributeMaxDynamicSharedMemorySize, SMEM_BYTES);
    cudaFuncSetAttribute(pass_kernel<false>,
                         cudaFuncAttributeMaxDynamicSharedMemorySize, SMEM_BYTES);

    dim3 pg(GX, BB / BG);          // (74, 4) = 296 blocks = 148 SMs x 2
    const int rb = SVOL / 256;     // 128 blocks for squash

    dummy_kernel<<<1, 32>>>();                           // #1 (aligns capture)

    pass_kernel<true><<<pg, 256, SMEM_BYTES>>>(x, W);    // #2: s0 (uniform c)
    squash_kernel<<<rb, 256>>>(out, 0);                  // #3: v0 -> Vsum

    pass_kernel<false><<<pg, 256, SMEM_BYTES>>>(x, W);   // #4: s1 (vs v0)
    squash_kernel<<<rb, 256>>>(out, 1);                  // #5: Vsum += v1

    pass_kernel<false><<<pg, 256, SMEM_BYTES>>>(x, W);   // #6: s2 (profiled)
    squash_kernel<<<rb, 256>>>(out, 2);                  // #7: v2 = output
}

// round 15
// speedup vs baseline: 2.4811x; 2.4811x over previous
#include <cuda_runtime.h>

// CapsuleLayer: x[B,I,D] fp32, W[I,O,D,K] fp32 -> v[B,O,K] fp32
// B=64, I=2048, D=8, O=32, K=16, 3 routing rounds.
// Round 15: pass 1 (uniform-c GEMM, no softmax) moved to tf32 tensor-core
// mma.sync.m16n8k8 (K=8 = D exactly; accumulator = s0 directly). Precision
// safe: pass-1 tf32 error reaches the output only via routing coefficients
// (second order ~1e-5). Passes 2-3 = proven fp32 R11 kernel, unchanged.

#define BB 64
#define II 2048
#define DD 8
#define OO 32
#define KK 16
#define BG 16            // b's per block
#define GX 74            // i-blocks; grid = 74 x 4 = 296 = 148 SMs x 2
#define NBUF 3
#define SVOL (BB*OO*KK)  // 32768

// ---- R11 (fp32 softmax pass) smem layout ----
#define WROWF 132                 // padded floats per o-row
#define WSLABF (OO*WROWF)         // 4224 floats (one i)
#define XROWF 12
#define XSLABF (BG*XROWF)         // 192 floats
#define SLABF  (WSLABF + XSLABF)  // 4416 floats
#define AG_OFF (NBUF*SLABF)       // 13248 floats
#define AGROW  33
#define SMEM_BYTES ((AG_OFF + BG*AGROW) * 4)   // 55104 B

// ---- pass1 MMA smem layout ----
#define W1F 4096                  // [o=32][d*16+k] = 128 floats per o, no pad
#define SLAB1F (W1F + BG*DD)      // + x[b=16][d=8] = 4224 floats
#define SMEM1_BYTES (NBUF * SLAB1F * 4)        // 50688 B

__device__ float g_part[GX * SVOL];  // per-i-block partial s (9.7 MB)
__device__ float g_vsum[SVOL];       // running sum of squashed v's

// ---------- packed f32x2 helpers ----------
__device__ __forceinline__ unsigned long long pk2(float lo, float hi) {
    unsigned long long r;
    asm("mov.b64 %0, {%1, %2};" : "=l"(r) : "f"(lo), "f"(hi));
    return r;
}
__device__ __forceinline__ void upk2(unsigned long long v, float& lo, float& hi) {
    asm("mov.b64 {%0, %1}, %2;" : "=f"(lo), "=f"(hi) : "l"(v));
}
__device__ __forceinline__ unsigned long long fma2(unsigned long long a,
                                                   unsigned long long b,
                                                   unsigned long long c) {
    unsigned long long d;
    asm("fma.rn.f32x2 %0, %1, %2, %3;" : "=l"(d) : "l"(a), "l"(b), "l"(c));
    return d;
}

// ---------- cp.async helpers ----------
__device__ __forceinline__ void cp16(unsigned dst_smem, const void* src) {
    asm volatile("cp.async.cg.shared.global [%0], [%1], 16;"
                 :: "r"(dst_smem), "l"(src));
}
__device__ __forceinline__ void cp_commit() {
    asm volatile("cp.async.commit_group;");
}
template<int N>
__device__ __forceinline__ void cp_wait() {
    asm volatile("cp.async.wait_group %0;" :: "n"(N) : "memory");
}

// ---------- tf32 helpers ----------
__device__ __forceinline__ unsigned f2tf32(float f) {
    unsigned u;
    asm("cvt.rna.tf32.f32 %0, %1;" : "=r"(u) : "f"(f));
    return u;
}
__device__ __forceinline__ void mma16n8k8(float* c, unsigned a0, unsigned a1,
                                          unsigned a2, unsigned a3,
                                          unsigned b0, unsigned b1) {
    asm volatile(
        "mma.sync.aligned.m16n8k8.row.col.f32.tf32.tf32.f32 "
        "{%0,%1,%2,%3}, {%4,%5,%6,%7}, {%8,%9}, {%0,%1,%2,%3};"
        : "+f"(c[0]), "+f"(c[1]), "+f"(c[2]), "+f"(c[3])
        : "r"(a0), "r"(a1), "r"(a2), "r"(a3), "r"(b0), "r"(b1));
}

// ================= pass 1: tf32 MMA GEMM =================
// Stage one i: W raw [o][128] + x [b][8]. One commit group.
__device__ __forceinline__ void fill1(unsigned sm_addr,
                                      const float* __restrict__ W,
                                      const float* __restrict__ x,
                                      int i, int buf, int t, int bg) {
#pragma unroll
    for (int r = 0; r < 4; r++) {
        int c = t + r * 256;
        int o = c >> 5, w16 = c & 31;
        const float* src = W + ((size_t)i * OO + o) * (DD * KK) + w16 * 4;
        unsigned dst = sm_addr + (unsigned)((buf * SLAB1F + o * 128 + w16 * 4) * 4);
        cp16(dst, src);
    }
    if (t < BG * 2) {
        int b = t >> 1, half = t & 1;
        const float* src = x + ((size_t)(bg * BG + b) * II + i) * DD + half * 4;
        unsigned dst = sm_addr +
            (unsigned)((buf * SLAB1F + W1F + b * DD + half * 4) * 4);
        cp16(dst, src);
    }
    cp_commit();
}

// 256 threads = 8 warps. Warp w owns n-tiles 8w..8w+7 (n = o*16+k, 64 tiles),
// all 16 b of this bg (one m-tile). One m16n8k8 MMA per (i, n-tile): K=8=d.
// Fragment maps (PTX m16n8k8 tf32): gr=lane>>2, tg=lane&3.
//   A: a0=(b=gr,d=tg) a1=(gr+8,tg) a2=(gr,tg+4) a3=(gr+8,tg+4)
//   B: b0=(d=tg, n=gr) b1=(d=tg+4, n=gr)
//   D: d0=(gr,2tg) d1=(gr,2tg+1) d2=(gr+8,2tg) d3=(gr+8,2tg+1)
__global__ __launch_bounds__(256, 2)
void pass1_mma_kernel(const float* __restrict__ x, const float* __restrict__ W) {
    extern __shared__ float sm[];
    const unsigned sm_addr = (unsigned)__cvta_generic_to_shared(sm);

    const int t  = threadIdx.x;
    const int w  = t >> 5;
    const int lane = t & 31;
    const int gr = lane >> 2;
    const int tg = lane & 3;
    const int bg = blockIdx.y;
    const int bx = blockIdx.x;
    const int ib = (bx * II) / GX;
    const int ie = ((bx + 1) * II) / GX;
    const int cnt = ie - ib;

    fill1(sm_addr, W, x, ib,     0, t, bg);
    fill1(sm_addr, W, x, ib + 1, 1, t, bg);

    float acc[8][4];
#pragma unroll
    for (int j = 0; j < 8; j++)
#pragma unroll
        for (int q = 0; q < 4; q++) acc[j][q] = 0.0f;

    cp_wait<1>();
    __syncthreads();

    for (int s = 0; s < cnt; s++) {
        if (s + 2 < cnt)
            fill1(sm_addr, W, x, ib + s + 2, (s + 2) % NBUF, t, bg);

        const float* slab = sm + (s % NBUF) * SLAB1F;
        const float* xs = slab + W1F;

        // A fragment: x[b][d]
        unsigned a0 = f2tf32(xs[gr * DD + tg]);
        unsigned a1 = f2tf32(xs[(gr + 8) * DD + tg]);
        unsigned a2 = f2tf32(xs[gr * DD + tg + 4]);
        unsigned a3 = f2tf32(xs[(gr + 8) * DD + tg + 4]);

#pragma unroll
        for (int j = 0; j < 8; j++) {
            int nt = w * 8 + j;
            int o  = nt >> 1;
            int k0 = (nt & 1) << 3;
            const float* wr = slab + o * 128;       // [d][k] row-major
            unsigned b0 = f2tf32(wr[tg * KK + k0 + gr]);
            unsigned b1 = f2tf32(wr[(tg + 4) * KK + k0 + gr]);
            mma16n8k8(acc[j], a0, a1, a2, a3, b0, b1);
        }

        if (s + 1 < cnt) cp_wait<1>(); else cp_wait<0>();
        __syncthreads();
    }

    // flush: s0 = acc/32 into g_part[bx][(b*OO+o)*KK + k]
    const float inv = 1.0f / (float)OO;
    const int b_lo = bg * BG + gr;
    const int b_hi = b_lo + 8;
#pragma unroll
    for (int j = 0; j < 8; j++) {
        int nt = w * 8 + j;
        int o  = nt >> 1;
        int kk = ((nt & 1) << 3) + 2 * tg;
        float2* p0 = reinterpret_cast<float2*>(
            g_part + (size_t)bx * SVOL + ((size_t)b_lo * OO + o) * KK + kk);
        float2* p1 = reinterpret_cast<float2*>(
            g_part + (size_t)bx * SVOL + ((size_t)b_hi * OO + o) * KK + kk);
        *p0 = make_float2(acc[j][0] * inv, acc[j][1] * inv);
        *p1 = make_float2(acc[j][2] * inv, acc[j][3] * inv);
    }
}

// ================= passes 2-3: proven R11 fp32 kernel =================
__device__ __forceinline__ void fill_slab(unsigned sm_addr,
                                          const float* __restrict__ W,
                                          const float* __restrict__ x,
                                          int i, int buf, int t, int bg) {
#pragma unroll
    for (int r = 0; r < 4; r++) {
        int c = t + r * 256;
        int o = c >> 5, w16 = c & 31;
        const float* src = W + ((size_t)i * OO + o) * (DD * KK) + w16 * 4;
        unsigned dst = sm_addr + (unsigned)((buf * SLABF + o * WROWF + w16 * 4) * 4);
        cp16(dst, src);
    }
    if (t < BG * 2) {
        int b = t >> 1, half = t & 1;
        const float* src = x + ((size_t)(bg * BG + b) * II + i) * DD + half * 4;
        unsigned dst = sm_addr +
            (unsigned)((buf * SLABF + WSLABF + b * XROWF + half * 4) * 4);
        cp16(dst, src);
    }
    cp_commit();
}

// 256 threads: t = o*8 + tb; thread handles b = tb, tb+8 (fp32, f32x2).
__global__ __launch_bounds__(256, 2)
void pass_kernel(const float* __restrict__ x, const float* __restrict__ W) {
    extern __shared__ float sm[];
    const unsigned sm_addr = (unsigned)__cvta_generic_to_shared(sm);
    float* ag = sm + AG_OFF;

    const int t  = threadIdx.x;
    const int o  = t >> 3;
    const int tb = t & 7;
    const int bg = blockIdx.y;
    const int b0 = bg * BG + tb;
    const int b1 = b0 + 8;

    const int bx = blockIdx.x;
    const int ib = (bx * II) / GX;
    const int ie = ((bx + 1) * II) / GX;
    const int cnt = ie - ib;

    fill_slab(sm_addr, W, x, ib,     0, t, bg);
    fill_slab(sm_addr, W, x, ib + 1, 1, t, bg);

    unsigned long long Va[8], Vb[8];
    {
        const ulonglong2* vp0 =
            reinterpret_cast<const ulonglong2*>(g_vsum + ((size_t)b0 * OO + o) * KK);
        const ulonglong2* vp1 =
            reinterpret_cast<const ulonglong2*>(g_vsum + ((size_t)b1 * OO + o) * KK);
#pragma unroll
        for (int j = 0; j < 4; j++) {
            ulonglong2 q0 = vp0[j]; Va[2*j] = q0.x; Va[2*j+1] = q0.y;
            ulonglong2 q1 = vp1[j]; Vb[2*j] = q1.x; Vb[2*j+1] = q1.y;
        }
    }

    unsigned long long sa[8], sb[8];
#pragma unroll
    for (int j = 0; j < 8; j++) { sa[j] = 0ull; sb[j] = 0ull; }

    for (int s = 0; s < cnt; s++) {
        if (s + 1 < cnt) cp_wait<1>(); else cp_wait<0>();
        __syncthreads();
        if (s + 2 < cnt)
            fill_slab(sm_addr, W, x, ib + s + 2, (s + 2) % NBUF, t, bg);

        const float* slab = sm + (s % NBUF) * SLABF;

        float xf0[8], xf1[8];
        {
            const float4* xr0 = reinterpret_cast<const float4*>(
                slab + WSLABF + tb * XROWF);
            const float4* xr1 = reinterpret_cast<const float4*>(
                slab + WSLABF + (tb + 8) * XROWF);
            float4 a0 = xr0[0], a1 = xr0[1];
            float4 c0 = xr1[0], c1 = xr1[1];
            xf0[0]=a0.x; xf0[1]=a0.y; xf0[2]=a0.z; xf0[3]=a0.w;
            xf0[4]=a1.x; xf0[5]=a1.y; xf0[6]=a1.z; xf0[7]=a1.w;
            xf1[0]=c0.x; xf1[1]=c0.y; xf1[2]=c0.z; xf1[3]=c0.w;
            xf1[4]=c1.x; xf1[5]=c1.y; xf1[6]=c1.z; xf1[7]=c1.w;
        }

        unsigned long long ua[8], ub[8];
#pragma unroll
        for (int j = 0; j < 8; j++) { ua[j] = 0ull; ub[j] = 0ull; }

        const float* wrow = slab + o * WROWF;
#pragma unroll
        for (int d = 0; d < DD; d++) {
            const ulonglong2* wp = reinterpret_cast<const ulonglong2*>(wrow + d * 16);
            unsigned long long xa2 = pk2(xf0[d], xf0[d]);
            unsigned long long xb2 = pk2(xf1[d], xf1[d]);
            ulonglong2 q0 = wp[0], q1 = wp[1];
            ua[0] = fma2(xa2, q0.x, ua[0]);  ub[0] = fma2(xb2, q0.x, ub[0]);
            ua[1] = fma2(xa2, q0.y, ua[1]);  ub[1] = fma2(xb2, q0.y, ub[1]);
            ua[2] = fma2(xa2, q1.x, ua[2]);  ub[2] = fma2(xb2, q1.x, ub[2]);
            ua[3] = fma2(xa2, q1.y, ua[3]);  ub[3] = fma2(xb2, q1.y, ub[3]);
            ulonglong2 q2 = wp[2], q3 = wp[3];
            ua[4] = fma2(xa2, q2.x, ua[4]);  ub[4] = fma2(xb2, q2.x, ub[4]);
            ua[5] = fma2(xa2, q2.y, ua[5]);  ub[5] = fma2(xb2, q2.y, ub[5]);
            ua[6] = fma2(xa2, q3.x, ua[6]);  ub[6] = fma2(xb2, q3.x, ub[6]);
            ua[7] = fma2(xa2, q3.y, ua[7]);  ub[7] = fma2(xb2, q3.y, ub[7]);
        }

        unsigned long long acca = 0ull, accb = 0ull;
#pragma unroll
        for (int j = 0; j < 8; j++) {
            acca = fma2(ua[j], Va[j], acca);
            accb = fma2(ub[j], Vb[j], accb);
        }
        float al, ah, bl2, bh;
        upk2(acca, al, ah);
        upk2(accb, bl2, bh);
        ag[tb * AGROW + o]       = al + ah;
        ag[(tb + 8) * AGROW + o] = bl2 + bh;
        __syncthreads();                 // barrier 1: agr visible

        {
            int sw = t >> 5, lane = t & 31;
            float e0 = __expf(ag[sw * AGROW + lane]);
            float e1 = __expf(ag[(sw + 8) * AGROW + lane]);
            float s0 = e0, s1 = e1;
#pragma unroll
            for (int st = 16; st > 0; st >>= 1) {
                s0 += __shfl_xor_sync(0xffffffffu, s0, st);
                s1 += __shfl_xor_sync(0xffffffffu, s1, st);
            }
            ag[sw * AGROW + lane]       = __fdividef(e0, s0);
            ag[(sw + 8) * AGROW + lane] = __fdividef(e1, s1);
        }
        __syncthreads();                 // barrier 2: c visible

        float ca = ag[tb * AGROW + o];
        float cb = ag[(tb + 8) * AGROW + o];
        unsigned long long c2a = pk2(ca, ca);
        unsigned long long c2b = pk2(cb, cb);

#pragma unroll
        for (int j = 0; j < 8; j++) {
            sa[j] = fma2(c2a, ua[j], sa[j]);
            sb[j] = fma2(c2b, ub[j], sb[j]);
        }
    }

    ulonglong2* p0 = reinterpret_cast<ulonglong2*>(
        g_part + ((size_t)bx * SVOL + ((size_t)b0 * OO + o) * KK));
    ulonglong2* p1 = reinterpret_cast<ulonglong2*>(
        g_part + ((size_t)bx * SVOL + ((size_t)b1 * OO + o) * KK));
    p0[0] = make_ulonglong2(sa[0], sa[1]);
    p0[1] = make_ulonglong2(sa[2], sa[3]);
    p0[2] = make_ulonglong2(sa[4], sa[5]);
    p0[3] = make_ulonglong2(sa[6], sa[7]);
    p1[0] = make_ulonglong2(sb[0], sb[1]);
    p1[1] = make_ulonglong2(sb[2], sb[3]);
    p1[2] = make_ulonglong2(sb[4], sb[5]);
    p1[3] = make_ulonglong2(sb[6], sb[7]);
}

// Reduce partials over GX=74 slabs (8 chains), squash over K=16.
// phase 0: vsum = v ; phase 1: vsum += v ; phase 2: out = v
__global__ void squash_kernel(float* __restrict__ out, int phase) {
    int idx = blockIdx.x * 256 + threadIdx.x;
    float a0 = 0.f, a1 = 0.f, a2 = 0.f, a3 = 0.f;
    float a4 = 0.f, a5 = 0.f, a6 = 0.f, a7 = 0.f;
#pragma unroll
    for (int p = 0; p + 8 <= GX; p += 8) {
        a0 += g_part[(size_t)(p + 0) * SVOL + idx];
        a1 += g_part[(size_t)(p + 1) * SVOL + idx];
        a2 += g_part[(size_t)(p + 2) * SVOL + idx];
        a3 += g_part[(size_t)(p + 3) * SVOL + idx];
        a4 += g_part[(size_t)(p + 4) * SVOL + idx];
        a5 += g_part[(size_t)(p + 5) * SVOL + idx];
        a6 += g_part[(size_t)(p + 6) * SVOL + idx];
        a7 += g_part[(size_t)(p + 7) * SVOL + idx];
    }
    a0 += g_part[(size_t)72 * SVOL + idx];
    a1 += g_part[(size_t)73 * SVOL + idx];
    float s = ((a0 + a1) + (a2 + a3)) + ((a4 + a5) + (a6 + a7));

    float s2 = s * s;
    s2 += __shfl_xor_sync(0xffffffffu, s2, 1);
    s2 += __shfl_xor_sync(0xffffffffu, s2, 2);
    s2 += __shfl_xor_sync(0xffffffffu, s2, 4);
    s2 += __shfl_xor_sync(0xffffffffu, s2, 8);

    float scale = s2 / ((1.0f + s2) * sqrtf(s2 + 1e-7f));
    float v = scale * s;

    if (phase == 0)      g_vsum[idx] = v;
    else if (phase == 1) g_vsum[idx] += v;
    else                 out[idx] = v;
}

// No-op: keeps ncu's -s 5 -c 1 capture window on pass#3 (softmax pass).
__global__ void dummy_kernel() {}

extern "C" void kernel_launch(void* const* d_in, const int* in_sizes, int n_in,
                              void* d_out, int out_size) {
    const float* a0 = (const float*)d_in[0];
    const float* a1 = (const float*)d_in[1];
    const float* x;
    const float* W;
    if (in_sizes[0] == BB * II * DD) { x = a0; W = a1; }
    else                             { x = a1; W = a0; }
    float* out = (float*)d_out;

    cudaFuncSetAttribute(pass1_mma_kernel,
                         cudaFuncAttributeMaxDynamicSharedMemorySize, SMEM1_BYTES);
    cudaFuncSetAttribute(pass_kernel,
                         cudaFuncAttributeMaxDynamicSharedMemorySize, SMEM_BYTES);

    dim3 pg(GX, BB / BG);          // (74, 4) = 296 blocks
    const int rb = SVOL / 256;     // 128 blocks for squash

    dummy_kernel<<<1, 32>>>();                            // #1 (aligns capture)

    pass1_mma_kernel<<<pg, 256, SMEM1_BYTES>>>(x, W);     // #2: s0 via tf32 MMA
    squash_kernel<<<rb, 256>>>(out, 0);                   // #3: v0 -> Vsum

    pass_kernel<<<pg, 256, SMEM_BYTES>>>(x, W);           // #4: s1 (fp32)
    squash_kernel<<<rb, 256>>>(out, 1);                   // #5: Vsum += v1

    pass_kernel<<<pg, 256, SMEM_BYTES>>>(x, W);           // #6: s2 (profiled)
    squash_kernel<<<rb, 256>>>(out, 2);                   // #7: v2 = output
}

// round 16
// speedup vs baseline: 3.0006x; 1.2094x over previous
#include <cuda_runtime.h>

// CapsuleLayer: x[B,I,D] fp32, W[I,O,D,K] fp32 -> v[B,O,K] fp32
// B=64, I=2048, D=8, O=32, K=16, 3 routing rounds.
// Round 16: ALL passes on tf32 tensor cores. Softmax passes: per i, 8
// non-accumulating m16n8k8 MMAs give u in fragments; agreement vs
// register-resident Vsum + quad shuffle-reduce + proven 2-barrier softmax;
// s accumulated in fp32 fragments. Fragment maps validated by R15 pass1.
// Fixed latent cp.async tail race (wait condition s+2<cnt).

#define BB 64
#define II 2048
#define DD 8
#define OO 32
#define KK 16
#define BG 16            // b's per block
#define GX 74            // i-blocks; grid = 74 x 4 = 296 = 148 SMs x 2
#define NBUF 3
#define SVOL (BB*OO*KK)  // 32768

// MMA smem layout (both pass kernels): W raw [o=32][128] + x [b=16][8]
#define W1F 4096
#define SLAB1F (W1F + BG*DD)       // 4224 floats
#define AGROW 33
#define SMEM1_BYTES (NBUF * SLAB1F * 4)                     // 50688 (pass1)
#define SMEM2_BYTES ((NBUF * SLAB1F + BG * AGROW) * 4)      // 52800 (softmax)

__device__ float g_part[GX * SVOL];  // per-i-block partial s (9.7 MB)
__device__ float g_vsum[SVOL];       // running sum of squashed v's

// ---------- cp.async helpers ----------
__device__ __forceinline__ void cp16(unsigned dst_smem, const void* src) {
    asm volatile("cp.async.cg.shared.global [%0], [%1], 16;"
                 :: "r"(dst_smem), "l"(src));
}
__device__ __forceinline__ void cp_commit() {
    asm volatile("cp.async.commit_group;");
}
template<int N>
__device__ __forceinline__ void cp_wait() {
    asm volatile("cp.async.wait_group %0;" :: "n"(N) : "memory");
}

// ---------- tf32 helpers ----------
__device__ __forceinline__ unsigned f2tf32(float f) {
    unsigned u;
    asm("cvt.rna.tf32.f32 %0, %1;" : "=r"(u) : "f"(f));
    return u;
}
// D = A*B + D (accumulating)
__device__ __forceinline__ void mma_acc(float* c, unsigned a0, unsigned a1,
                                        unsigned a2, unsigned a3,
                                        unsigned b0, unsigned b1) {
    asm volatile(
        "mma.sync.aligned.m16n8k8.row.col.f32.tf32.tf32.f32 "
        "{%0,%1,%2,%3}, {%4,%5,%6,%7}, {%8,%9}, {%0,%1,%2,%3};"
        : "+f"(c[0]), "+f"(c[1]), "+f"(c[2]), "+f"(c[3])
        : "r"(a0), "r"(a1), "r"(a2), "r"(a3), "r"(b0), "r"(b1));
}
// D = A*B (zero C)
__device__ __forceinline__ void mma_z(float* d, unsigned a0, unsigned a1,
                                      unsigned a2, unsigned a3,
                                      unsigned b0, unsigned b1) {
    asm volatile(
        "mma.sync.aligned.m16n8k8.row.col.f32.tf32.tf32.f32 "
        "{%0,%1,%2,%3}, {%4,%5,%6,%7}, {%8,%9}, {%10,%10,%10,%10};"
        : "=f"(d[0]), "=f"(d[1]), "=f"(d[2]), "=f"(d[3])
        : "r"(a0), "r"(a1), "r"(a2), "r"(a3), "r"(b0), "r"(b1), "f"(0.0f));
}

// Stage one i: W raw [o][128] + x [b][8]. One commit group. 256 threads.
__device__ __forceinline__ void fill1(unsigned sm_addr,
                                      const float* __restrict__ W,
                                      const float* __restrict__ x,
                                      int i, int buf, int t, int bg) {
#pragma unroll
    for (int r = 0; r < 4; r++) {
        int c = t + r * 256;
        int o = c >> 5, w16 = c & 31;
        const float* src = W + ((size_t)i * OO + o) * (DD * KK) + w16 * 4;
        unsigned dst = sm_addr + (unsigned)((buf * SLAB1F + o * 128 + w16 * 4) * 4);
        cp16(dst, src);
    }
    if (t < BG * 2) {
        int b = t >> 1, half = t & 1;
        const float* src = x + ((size_t)(bg * BG + b) * II + i) * DD + half * 4;
        unsigned dst = sm_addr +
            (unsigned)((buf * SLAB1F + W1F + b * DD + half * 4) * 4);
        cp16(dst, src);
    }
    cp_commit();
}

// Fragment maps (PTX m16n8k8 tf32), gr=lane>>2, tg=lane&3:
//   A: a0=(b=gr,d=tg) a1=(gr+8,tg) a2=(gr,tg+4) a3=(gr+8,tg+4)
//   B (tile nt: o=nt>>1, k0=(nt&1)*8): b0=(d=tg,k0+gr) b1=(d=tg+4,k0+gr)
//   D: d0=(gr,k0+2tg) d1=(gr,k0+2tg+1) d2=(gr+8,k0+2tg) d3=(gr+8,k0+2tg+1)

// ============ pass 1: uniform-c GEMM (accumulating over i) ============
__global__ __launch_bounds__(256, 2)
void pass1_mma_kernel(const float* __restrict__ x, const float* __restrict__ W) {
    extern __shared__ float sm[];
    const unsigned sm_addr = (unsigned)__cvta_generic_to_shared(sm);

    const int t  = threadIdx.x;
    const int w  = t >> 5;
    const int lane = t & 31;
    const int gr = lane >> 2;
    const int tg = lane & 3;
    const int bg = blockIdx.y;
    const int bx = blockIdx.x;
    const int ib = (bx * II) / GX;
    const int ie = ((bx + 1) * II) / GX;
    const int cnt = ie - ib;

    fill1(sm_addr, W, x, ib,     0, t, bg);
    fill1(sm_addr, W, x, ib + 1, 1, t, bg);

    float acc[8][4];
#pragma unroll
    for (int j = 0; j < 8; j++)
#pragma unroll
        for (int q = 0; q < 4; q++) acc[j][q] = 0.0f;

    cp_wait<1>();
    __syncthreads();

    for (int s = 0; s < cnt; s++) {
        if (s + 2 < cnt)
            fill1(sm_addr, W, x, ib + s + 2, (s + 2) % NBUF, t, bg);

        const float* slab = sm + (s % NBUF) * SLAB1F;
        const float* xs = slab + W1F;

        unsigned a0 = f2tf32(xs[gr * DD + tg]);
        unsigned a1 = f2tf32(xs[(gr + 8) * DD + tg]);
        unsigned a2 = f2tf32(xs[gr * DD + tg + 4]);
        unsigned a3 = f2tf32(xs[(gr + 8) * DD + tg + 4]);

#pragma unroll
        for (int j = 0; j < 8; j++) {
            int nt = w * 8 + j;
            int o  = nt >> 1;
            int k0 = (nt & 1) << 3;
            const float* wr = slab + o * 128;
            unsigned b0 = f2tf32(wr[tg * KK + k0 + gr]);
            unsigned b1 = f2tf32(wr[(tg + 4) * KK + k0 + gr]);
            mma_acc(acc[j], a0, a1, a2, a3, b0, b1);
        }

        if (s + 2 < cnt) cp_wait<1>(); else cp_wait<0>();
        __syncthreads();
    }

    const float inv = 1.0f / (float)OO;
    const int b_lo = bg * BG + gr;
    const int b_hi = b_lo + 8;
#pragma unroll
    for (int j = 0; j < 8; j++) {
        int nt = w * 8 + j;
        int o  = nt >> 1;
        int kk = ((nt & 1) << 3) + 2 * tg;
        float2* p0 = reinterpret_cast<float2*>(
            g_part + (size_t)bx * SVOL + ((size_t)b_lo * OO + o) * KK + kk);
        float2* p1 = reinterpret_cast<float2*>(
            g_part + (size_t)bx * SVOL + ((size_t)b_hi * OO + o) * KK + kk);
        *p0 = make_float2(acc[j][0] * inv, acc[j][1] * inv);
        *p1 = make_float2(acc[j][2] * inv, acc[j][3] * inv);
    }
}

// ============ passes 2-3: softmax routing pass via MMA ============
// Per i: u = MMA (fresh), agreement vs reg-resident Vsum, quad shfl-reduce,
// block softmax over o (2 barriers), s-fragment accumulate.
__global__ __launch_bounds__(256, 2)
void pass_mma_kernel(const float* __restrict__ x, const float* __restrict__ W) {
    extern __shared__ float sm[];
    const unsigned sm_addr = (unsigned)__cvta_generic_to_shared(sm);
    float* ag = sm + NBUF * SLAB1F;

    const int t  = threadIdx.x;
    const int w  = t >> 5;
    const int lane = t & 31;
    const int gr = lane >> 2;
    const int tg = lane & 3;
    const int bg = blockIdx.y;
    const int bx = blockIdx.x;
    const int ib = (bx * II) / GX;
    const int ie = ((bx + 1) * II) / GX;
    const int cnt = ie - ib;

    fill1(sm_addr, W, x, ib,     0, t, bg);
    fill1(sm_addr, W, x, ib + 1, 1, t, bg);

    const int b_lo = bg * BG + gr;
    const int b_hi = b_lo + 8;

    // Vsum slices this thread needs: VA/VB[jo][{2tg,2tg+1,8+2tg,8+2tg+1}]
    float VA[4][4], VB[4][4];
#pragma unroll
    for (int jo = 0; jo < 4; jo++) {
        int o = 4 * w + jo;
        const float2* vpA = reinterpret_cast<const float2*>(
            g_vsum + ((size_t)b_lo * OO + o) * KK);
        const float2* vpB = reinterpret_cast<const float2*>(
            g_vsum + ((size_t)b_hi * OO + o) * KK);
        float2 qa0 = vpA[tg], qa1 = vpA[4 + tg];
        float2 qb0 = vpB[tg], qb1 = vpB[4 + tg];
        VA[jo][0] = qa0.x; VA[jo][1] = qa0.y; VA[jo][2] = qa1.x; VA[jo][3] = qa1.y;
        VB[jo][0] = qb0.x; VB[jo][1] = qb0.y; VB[jo][2] = qb1.x; VB[jo][3] = qb1.y;
    }

    float sacc[8][4];
#pragma unroll
    for (int j = 0; j < 8; j++)
#pragma unroll
        for (int q = 0; q < 4; q++) sacc[j][q] = 0.0f;

    cp_wait<1>();
    __syncthreads();

    for (int s = 0; s < cnt; s++) {
        if (s + 2 < cnt)
            fill1(sm_addr, W, x, ib + s + 2, (s + 2) % NBUF, t, bg);

        const float* slab = sm + (s % NBUF) * SLAB1F;
        const float* xs = slab + W1F;

        unsigned a0 = f2tf32(xs[gr * DD + tg]);
        unsigned a1 = f2tf32(xs[(gr + 8) * DD + tg]);
        unsigned a2 = f2tf32(xs[gr * DD + tg + 4]);
        unsigned a3 = f2tf32(xs[(gr + 8) * DD + tg + 4]);

        float u[8][4];
#pragma unroll
        for (int j = 0; j < 8; j++) {
            int nt = w * 8 + j;
            int o  = nt >> 1;
            int k0 = (nt & 1) << 3;
            const float* wr = slab + o * 128;
            unsigned b0 = f2tf32(wr[tg * KK + k0 + gr]);
            unsigned b1 = f2tf32(wr[(tg + 4) * KK + k0 + gr]);
            mma_z(u[j], a0, a1, a2, a3, b0, b1);
        }

        // agreement partials: agA/agB[jo] = u . Vsum over this thread's k's
        float agA[4], agB[4];
#pragma unroll
        for (int jo = 0; jo < 4; jo++) {
            int j0 = 2 * jo, j1 = 2 * jo + 1;
            agA[jo] = u[j0][0] * VA[jo][0] + u[j0][1] * VA[jo][1]
                    + u[j1][0] * VA[jo][2] + u[j1][1] * VA[jo][3];
            agB[jo] = u[j0][2] * VB[jo][0] + u[j0][3] * VB[jo][1]
                    + u[j1][2] * VB[jo][2] + u[j1][3] * VB[jo][3];
        }
        // reduce over the 4-lane quad (lanes gr*4 + tg, tg = 0..3)
#pragma unroll
        for (int jo = 0; jo < 4; jo++) {
            agA[jo] += __shfl_xor_sync(0xffffffffu, agA[jo], 1);
            agA[jo] += __shfl_xor_sync(0xffffffffu, agA[jo], 2);
            agB[jo] += __shfl_xor_sync(0xffffffffu, agB[jo], 1);
            agB[jo] += __shfl_xor_sync(0xffffffffu, agB[jo], 2);
        }
        if (tg == 0) {
#pragma unroll
            for (int jo = 0; jo < 4; jo++) {
                ag[gr * AGROW + 4 * w + jo]       = agA[jo];
                ag[(gr + 8) * AGROW + 4 * w + jo] = agB[jo];
            }
        }
        __syncthreads();                 // barrier 1: agr visible

        // warp sw: softmax rows sw, sw+8 (lane = o). No max-subtract:
        // |agr| <= |u||Vsum| = O(1), exp safe in fp32.
        {
            float e0 = __expf(ag[w * AGROW + lane]);
            float e1 = __expf(ag[(w + 8) * AGROW + lane]);
            float s0 = e0, s1 = e1;
#pragma unroll
            for (int st = 16; st > 0; st >>= 1) {
                s0 += __shfl_xor_sync(0xffffffffu, s0, st);
                s1 += __shfl_xor_sync(0xffffffffu, s1, st);
            }
            ag[w * AGROW + lane]       = __fdividef(e0, s0);
            ag[(w + 8) * AGROW + lane] = __fdividef(e1, s1);
        }
        if (s + 2 < cnt) cp_wait<1>(); else cp_wait<0>();
        __syncthreads();                 // barrier 2: c + next slab visible

        float cA[4], cB[4];
#pragma unroll
        for (int jo = 0; jo < 4; jo++) {
            cA[jo] = ag[gr * AGROW + 4 * w + jo];
            cB[jo] = ag[(gr + 8) * AGROW + 4 * w + jo];
        }
#pragma unroll
        for (int j = 0; j < 8; j++) {
            int jo = j >> 1;
            sacc[j][0] = fmaf(cA[jo], u[j][0], sacc[j][0]);
            sacc[j][1] = fmaf(cA[jo], u[j][1], sacc[j][1]);
            sacc[j][2] = fmaf(cB[jo], u[j][2], sacc[j][2]);
            sacc[j][3] = fmaf(cB[jo], u[j][3], sacc[j][3]);
        }
    }

#pragma unroll
    for (int j = 0; j < 8; j++) {
        int nt = w * 8 + j;
        int o  = nt >> 1;
        int kk = ((nt & 1) << 3) + 2 * tg;
        float2* p0 = reinterpret_cast<float2*>(
            g_part + (size_t)bx * SVOL + ((size_t)b_lo * OO + o) * KK + kk);
        float2* p1 = reinterpret_cast<float2*>(
            g_part + (size_t)bx * SVOL + ((size_t)b_hi * OO + o) * KK + kk);
        *p0 = make_float2(sacc[j][0], sacc[j][1]);
        *p1 = make_float2(sacc[j][2], sacc[j][3]);
    }
}

// Reduce partials over GX=74 slabs (8 chains), squash over K=16.
// phase 0: vsum = v ; phase 1: vsum += v ; phase 2: out = v
__global__ void squash_kernel(float* __restrict__ out, int phase) {
    int idx = blockIdx.x * 256 + threadIdx.x;
    float a0 = 0.f, a1 = 0.f, a2 = 0.f, a3 = 0.f;
    float a4 = 0.f, a5 = 0.f, a6 = 0.f, a7 = 0.f;
#pragma unroll
    for (int p = 0; p + 8 <= GX; p += 8) {
        a0 += g_part[(size_t)(p + 0) * SVOL + idx];
        a1 += g_part[(size_t)(p + 1) * SVOL + idx];
        a2 += g_part[(size_t)(p + 2) * SVOL + idx];
        a3 += g_part[(size_t)(p + 3) * SVOL + idx];
        a4 += g_part[(size_t)(p + 4) * SVOL + idx];
        a5 += g_part[(size_t)(p + 5) * SVOL + idx];
        a6 += g_part[(size_t)(p + 6) * SVOL + idx];
        a7 += g_part[(size_t)(p + 7) * SVOL + idx];
    }
    a0 += g_part[(size_t)72 * SVOL + idx];
    a1 += g_part[(size_t)73 * SVOL + idx];
    float s = ((a0 + a1) + (a2 + a3)) + ((a4 + a5) + (a6 + a7));

    float s2 = s * s;
    s2 += __shfl_xor_sync(0xffffffffu, s2, 1);
    s2 += __shfl_xor_sync(0xffffffffu, s2, 2);
    s2 += __shfl_xor_sync(0xffffffffu, s2, 4);
    s2 += __shfl_xor_sync(0xffffffffu, s2, 8);

    float scale = s2 / ((1.0f + s2) * sqrtf(s2 + 1e-7f));
    float v = scale * s;

    if (phase == 0)      g_vsum[idx] = v;
    else if (phase == 1) g_vsum[idx] += v;
    else                 out[idx] = v;
}

// No-op: keeps ncu's -s 5 -c 1 capture window on pass#3 (softmax pass).
__global__ void dummy_kernel() {}

extern "C" void kernel_launch(void* const* d_in, const int* in_sizes, int n_in,
                              void* d_out, int out_size) {
    const float* a0 = (const float*)d_in[0];
    const float* a1 = (const float*)d_in[1];
    const float* x;
    const float* W;
    if (in_sizes[0] == BB * II * DD) { x = a0; W = a1; }
    else                             { x = a1; W = a0; }
    float* out = (float*)d_out;

    cudaFuncSetAttribute(pass1_mma_kernel,
                         cudaFuncAttributeMaxDynamicSharedMemorySize, SMEM1_BYTES);
    cudaFuncSetAttribute(pass_mma_kernel,
                         cudaFuncAttributeMaxDynamicSharedMemorySize, SMEM2_BYTES);

    dim3 pg(GX, BB / BG);          // (74, 4) = 296 blocks
    const int rb = SVOL / 256;     // 128 blocks for squash

    dummy_kernel<<<1, 32>>>();                            // #1 (aligns capture)

    pass1_mma_kernel<<<pg, 256, SMEM1_BYTES>>>(x, W);     // #2: s0 via MMA
    squash_kernel<<<rb, 256>>>(out, 0);                   // #3: v0 -> Vsum

    pass_mma_kernel<<<pg, 256, SMEM2_BYTES>>>(x, W);      // #4: s1 via MMA
    squash_kernel<<<rb, 256>>>(out, 1);                   // #5: Vsum += v1

    pass_mma_kernel<<<pg, 256, SMEM2_BYTES>>>(x, W);      // #6: s2 (profiled)
    squash_kernel<<<rb, 256>>>(out, 2);                   // #7: v2 = output
}